// round 7
// baseline (speedup 1.0000x reference)
#include <cuda_runtime.h>
#include <cstdint>

#define BB 1024
#define LL 512
#define TT 50
#define NT 48
#define START_TAG 48
#define STOP_TAG  49

typedef unsigned long long u64;

__device__ float g_nll[BB];
__device__ int   g_perm[BB];
__device__ int   g_done;          // zero-init; reset by last CTA each launch

__device__ __forceinline__ u64 pack2(float x, float y) {
    u64 u; asm("mov.b64 %0, {%1,%2};" : "=l"(u) : "f"(x), "f"(y)); return u;
}
__device__ __forceinline__ void unpack2(u64 u, float &x, float &y) {
    asm("mov.b64 {%0,%1}, %2;" : "=f"(x), "=f"(y) : "l"(u));
}
__device__ __forceinline__ u64 fma2(u64 a, u64 b, u64 c) {
    u64 d; asm("fma.rn.f32x2 %0, %1, %2, %3;" : "=l"(d) : "l"(a), "l"(b), "l"(c)); return d;
}
// warp max of NON-NEGATIVE floats via single integer redux
__device__ __forceinline__ float warp_max_pos(float x) {
    int r; asm("redux.sync.max.s32 %0, %1, 0xffffffff;" : "=r"(r) : "r"(__float_as_int(x)));
    return __int_as_float(r);
}

// ---------- scheduling: counting sort by descending len (2-barrier scan) ----------
__global__ __launch_bounds__(1024) void crf_sort_kernel(const int* __restrict__ lens) {
    __shared__ int hist[512];
    __shared__ int wsum[16];
    const int tid = threadIdx.x;
    if (tid < 512) hist[tid] = 0;
    __syncthreads();
    const int key = 512 - lens[tid];        // len [1,512] -> key [0,511], descending
    atomicAdd(&hist[key], 1);
    __syncthreads();
    int v = 0, orig = 0;
    if (tid < 512) {
        orig = hist[tid];
        v = orig;
#pragma unroll
        for (int o = 1; o < 32; o <<= 1) {  // warp inclusive scan
            int n = __shfl_up_sync(0xffffffffu, v, o);
            if ((tid & 31) >= o) v += n;
        }
        if ((tid & 31) == 31) wsum[tid >> 5] = v;
    }
    __syncthreads();
    if (tid < 16) {
        int s = wsum[tid];
#pragma unroll
        for (int o = 1; o < 16; o <<= 1) {
            int n = __shfl_up_sync(0x0000ffffu, s, o);
            if (tid >= o) s += n;
        }
        wsum[tid] = s;
    }
    __syncthreads();
    if (tid < 512) {
        int base = (tid >= 32) ? wsum[(tid >> 5) - 1] : 0;
        hist[tid] = base + v - orig;        // exclusive prefix
    }
    __syncthreads();
    int pos = atomicAdd(&hist[key], 1);
    g_perm[pos] = tid;
}

// ---------- 48x48 matvec, 8 accumulator chains (dep depth 6 / 3) ----------
// Lane pair (2m,2m+1): lane fully owns jF=3m+(l&1); shared jS=3m+2 split over
// k-halves (shb) and combined with one shfl.
__device__ __forceinline__ void matvec48(const u64* __restrict__ rF,
                                         const u64* __restrict__ rS,
                                         const ulonglong2* __restrict__ sb,
                                         int shb, bool odd,
                                         float& pF, float& pSh)
{
    const u64 ONE = pack2(1.0f, 1.0f);
    u64 a0 = 0ull, a1 = 0ull, a2 = 0ull, a3 = 0ull;
#pragma unroll
    for (int q = 0; q < 12; q++) {
        ulonglong2 v = sb[q];
        if (q & 1) {
            a2 = fma2(rF[2 * q],     v.x, a2);
            a3 = fma2(rF[2 * q + 1], v.y, a3);
        } else {
            a0 = fma2(rF[2 * q],     v.x, a0);
            a1 = fma2(rF[2 * q + 1], v.y, a1);
        }
    }
    u64 b0 = 0ull, b1 = 0ull, b2 = 0ull, b3 = 0ull;
#pragma unroll
    for (int q = 0; q < 6; q++) {
        ulonglong2 v = sb[shb + q];
        if (q & 1) {
            b2 = fma2(rS[2 * q],     v.x, b2);
            b3 = fma2(rS[2 * q + 1], v.y, b3);
        } else {
            b0 = fma2(rS[2 * q],     v.x, b0);
            b1 = fma2(rS[2 * q + 1], v.y, b1);
        }
    }
    u64 af = fma2(ONE, fma2(ONE, a2, a0), fma2(ONE, a3, a1));
    float f0, f1; unpack2(af, f0, f1);
    pF = f0 + f1;
    u64 ash = fma2(ONE, fma2(ONE, b2, b0), fma2(ONE, b3, b1));
    float g0, g1; unpack2(ash, g0, g1);
    float ph = g0 + g1;
    pSh = ph + __shfl_xor_sync(0xffffffffu, ph, 1);
}

// ---------- generic chain runner ----------
__device__ __forceinline__ void run_steps(
    int nsteps, const float* __restrict__ lg, int base, int dir,
    const u64* __restrict__ rF, const u64* __restrict__ rS,
    u64 (*buf)[24], int shb, bool odd, int jF, int jS,
    float& sF, float& sS, int& E, float& sc)
{
    if (nsteps <= 0) return;

    float pfF[2], pfS[2];
    {
        int i1 = base + dir;
        int i2 = base + dir * min(2, nsteps);
        pfF[1] = lg[(size_t)i1 * TT + jF];
        pfS[1] = odd ? lg[(size_t)i1 * TT + jS] : 0.0f;
        pfF[0] = lg[(size_t)i2 * TT + jF];
        pfS[0] = odd ? lg[(size_t)i2 * TT + jS] : 0.0f;
    }

#pragma unroll 4
    for (int t = 1; t <= nsteps; t++) {
        float emF = __expf(pfF[t & 1]) * sc;
        float emS = __expf(pfS[t & 1]) * sc;
        sc = 1.0f;
        {
            int tp = min(t + 2, nsteps);
            const float* rp = lg + (size_t)(base + dir * tp) * TT;
            pfF[t & 1] = rp[jF];
            pfS[t & 1] = odd ? rp[jS] : 0.0f;
        }
        float pF, pSh;
        matvec48(rF, rS, (const ulonglong2*)buf[t & 1], shb, odd, pF, pSh);
        sF = pF * emF;
        sS = odd ? (pSh * emS) : 0.0f;
        float* sw = (float*)buf[(t + 1) & 1];
        sw[jF] = sF;
        if (odd) sw[jS] = sS;
        if ((t & 3) == 3) {                    // lazy exact power-of-2 renorm
            float mx = warp_max_pos(fmaxf(sF, sS));
            int e = (__float_as_int(mx) >> 23) - 127;
            sc = __int_as_float((127 - e) << 23);
            E += e;
        }
        __syncwarp();
    }
}

// ---------- fwd/bwd split kernel + fused final reduction ----------
__global__ __launch_bounds__(64) void crf_fwd_kernel(
    const float* __restrict__ logits,   // [B, L, T]
    const float* __restrict__ trans,    // [T, T]
    const int*   __restrict__ labels,   // [B, L]
    const int*   __restrict__ lens,     // [B]
    float*       __restrict__ out)      // [1]
{
    __shared__ __align__(16) u64 bufF[2][24];
    __shared__ __align__(16) u64 bufB[2][24];
    __shared__ float sfin[NT];
    __shared__ float sgold;
    __shared__ int   sEf;
    __shared__ int   sLast;
    __shared__ float sred[2];

    const int  tid = threadIdx.x;
    const int  l   = tid & 31;
    const int  w   = tid >> 5;
    const int  m_  = l >> 1;
    const bool odd = (l & 1);
    const int  jF  = 3 * m_ + (odd ? 1 : 0);
    const int  jS  = 3 * m_ + 2;
    const int  shb = odd ? 6 : 0;

    const int b   = g_perm[blockIdx.x];
    const int len = lens[b];
    const float* lg = logits + (size_t)b * (LL * TT);
    const int mS  = (len + 1) >> 1;

    float rFv = 0.0f, rSv = 0.0f;
    int   Eb  = 0;

    if (w == 0) {
        // -------- forward half --------
        u64 rF[24], rS[12];
#pragma unroll
        for (int kk = 0; kk < 24; kk++)
            rF[kk] = pack2(__expf(trans[jF * TT + 2 * kk]),
                           __expf(trans[jF * TT + 2 * kk + 1]));
#pragma unroll
        for (int q = 0; q < 12; q++) {
            int kk = shb * 2 + q;
            rS[q] = pack2(__expf(trans[jS * TT + 2 * kk]),
                          __expf(trans[jS * TT + 2 * kk + 1]));
        }

        float sF = __expf(trans[jF * TT + START_TAG] + lg[jF]);
        float sS = odd ? __expf(trans[jS * TT + START_TAG] + lg[jS]) : 0.0f;
        float* sw = (float*)bufF[1];
        sw[jF] = sF;
        if (odd) sw[jS] = sS;
        __syncwarp();

        int E = 0; float sc = 1.0f;
        run_steps(mS - 1, lg, 0, +1, rF, rS, bufF, shb, odd, jF, jS, sF, sS, E, sc);
        sF *= sc; sS *= sc;
        sfin[jF] = sF;
        if (odd) sfin[jS] = sS;
        if (l == 0) sEf = E;

        // gold score
        const int* labs = labels + (size_t)b * LL;
        float gold = 0.0f;
        for (int t2 = l; t2 < len; t2 += 32) {
            int lab  = labs[t2];
            int prev = t2 ? labs[t2 - 1] : START_TAG;
            gold += lg[(size_t)t2 * TT + lab] + trans[lab * TT + prev];
        }
#pragma unroll
        for (int o = 16; o; o >>= 1) gold += __shfl_xor_sync(0xffffffffu, gold, o);
        if (l == 0) sgold = gold + trans[STOP_TAG * TT + labs[len - 1]];
    } else {
        // -------- backward half (transposed coefficients) --------
        u64 rF[24], rS[12];
#pragma unroll
        for (int kk = 0; kk < 24; kk++)
            rF[kk] = pack2(__expf(trans[(2 * kk) * TT + jF]),
                           __expf(trans[(2 * kk + 1) * TT + jF]));
#pragma unroll
        for (int q = 0; q < 12; q++) {
            int kk = shb * 2 + q;
            rS[q] = pack2(__expf(trans[(2 * kk) * TT + jS]),
                          __expf(trans[(2 * kk + 1) * TT + jS]));
        }

        if (len == 1) {
            rFv = __expf(trans[STOP_TAG * TT + jF]);
            rSv = __expf(trans[STOP_TAG * TT + jS]);
        } else {
            float sF = __expf(trans[STOP_TAG * TT + jF] + lg[(size_t)(len - 1) * TT + jF]);
            float sS = odd ? __expf(trans[STOP_TAG * TT + jS] + lg[(size_t)(len - 1) * TT + jS]) : 0.0f;
            float* sw = (float*)bufB[1];
            sw[jF] = sF;
            if (odd) sw[jS] = sS;
            __syncwarp();

            float sc = 1.0f;
            const int nb = len - 1 - mS;
            run_steps(nb, lg, len - 1, -1, rF, rS, bufB, shb, odd, jF, jS, sF, sS, Eb, sc);

            float pF, pSh;
            matvec48(rF, rS, (const ulonglong2*)bufB[(nb + 1) & 1], shb, odd, pF, pSh);
            rFv = pF * sc;
            rSv = pSh * sc;
        }
    }

    __syncthreads();

    if (w == 1) {
        float d = rFv * sfin[jF] + (odd ? rSv * sfin[jS] : 0.0f);
#pragma unroll
        for (int o = 16; o; o >>= 1) d += __shfl_xor_sync(0xffffffffu, d, o);
        if (l == 0) {
            float partition = logf(d) + (float)(Eb + sEf) * 0.69314718055994530942f;
            g_nll[b] = partition - sgold;
            __threadfence();                 // g_nll visible device-wide
        }
    }
    __syncthreads();

    // ---- last CTA performs the deterministic final reduction
    if (tid == 0) {
        int c = atomicAdd(&g_done, 1);
        sLast = (c == BB - 1);
    }
    __syncthreads();
    if (sLast) {
        __threadfence();
        float s = 0.0f;
        for (int i = tid; i < BB; i += 64) s += g_nll[i];   // fixed order
#pragma unroll
        for (int o = 16; o; o >>= 1) s += __shfl_xor_sync(0xffffffffu, s, o);
        if (l == 0) sred[w] = s;
        __syncthreads();
        if (tid == 0) {
            out[0] = (sred[0] + sred[1]) / (float)BB;
            g_done = 0;                       // reset for next replay
        }
    }
}

extern "C" void kernel_launch(void* const* d_in, const int* in_sizes, int n_in,
                              void* d_out, int out_size) {
    const float* logits = (const float*)d_in[0];
    const float* trans  = (const float*)d_in[1];
    const int*   labels = (const int*)d_in[2];
    const int*   lens   = (const int*)d_in[3];

    crf_sort_kernel<<<1, 1024>>>(lens);
    crf_fwd_kernel<<<BB, 64>>>(logits, trans, labels, lens, (float*)d_out);
}